// round 15
// baseline (speedup 1.0000x reference)
#include <cuda_runtime.h>
#include <cuda_bf16.h>
#include <math.h>
#include <stdint.h>

#define D_DIM 768
#define T_MAX 8192
#define NT 256

// Scratch (__device__ globals per harness rules)
__device__ __nv_bfloat16 g_Qhi[(size_t)T_MAX * D_DIM];
__device__ __nv_bfloat16 g_Qlo[(size_t)T_MAX * D_DIM];
__device__ __nv_bfloat16 g_Ehi[(size_t)T_MAX * D_DIM];
__device__ __nv_bfloat16 g_Elo[(size_t)T_MAX * D_DIM];
__device__ __nv_bfloat16 g_Whi[(size_t)D_DIM * D_DIM];
__device__ __nv_bfloat16 g_Wlo[(size_t)D_DIM * D_DIM];
// Score band K-split x4 partials: Band[t][d+32] = Q[t] . E[t+d], d in [-32,32)
__device__ float g_Band0[(size_t)T_MAX * 64];
__device__ float g_Band1[(size_t)T_MAX * 64];
__device__ float g_Band2[(size_t)T_MAX * 64];
__device__ float g_Band3[(size_t)T_MAX * 64];

// ---------------------------------------------------------------------------
// Helpers (baseline PTX only — plain sm_103 target)
// ---------------------------------------------------------------------------
__device__ __forceinline__ uint32_t smem_u32(const void* p) {
    uint32_t a;
    asm("{ .reg .u64 t; cvta.to.shared.u64 t, %1; cvt.u32.u64 %0, t; }"
        : "=r"(a) : "l"(p));
    return a;
}
__device__ __forceinline__ void ldmx4(uint32_t* r, uint32_t addr) {
    asm volatile("ldmatrix.sync.aligned.m8n8.x4.shared.b16 {%0,%1,%2,%3}, [%4];"
                 : "=r"(r[0]), "=r"(r[1]), "=r"(r[2]), "=r"(r[3]) : "r"(addr));
}
__device__ __forceinline__ void mma16816(float* c, const uint32_t* a,
                                         const uint32_t* b) {
    asm volatile(
        "mma.sync.aligned.m16n8k16.row.col.f32.bf16.bf16.f32 "
        "{%0,%1,%2,%3}, {%4,%5,%6,%7}, {%8,%9}, {%0,%1,%2,%3};"
        : "+f"(c[0]), "+f"(c[1]), "+f"(c[2]), "+f"(c[3])
        : "r"(a[0]), "r"(a[1]), "r"(a[2]), "r"(a[3]), "r"(b[0]), "r"(b[1]));
}
__device__ __forceinline__ void cp16(uint32_t dst, const void* src) {
    asm volatile("cp.async.cg.shared.global [%0], [%1], 16;"
                 :: "r"(dst), "l"(src) : "memory");
}
#define CP_COMMIT() asm volatile("cp.async.commit_group;" ::: "memory")
#define CP_WAIT0()  asm volatile("cp.async.wait_group 0;" ::: "memory")

// ---------------------------------------------------------------------------
// Kernel 0: fp32 -> (bf16 hi, bf16 lo) split
// ---------------------------------------------------------------------------
__global__ __launch_bounds__(256) void cvt_kernel(
    const float* __restrict__ src, __nv_bfloat16* __restrict__ hi,
    __nv_bfloat16* __restrict__ lo, int n4)
{
    int i = blockIdx.x * blockDim.x + threadIdx.x;
    if (i >= n4) return;
    float4 v = reinterpret_cast<const float4*>(src)[i];
    __nv_bfloat16 h0 = __float2bfloat16_rn(v.x);
    __nv_bfloat16 h1 = __float2bfloat16_rn(v.y);
    __nv_bfloat16 h2 = __float2bfloat16_rn(v.z);
    __nv_bfloat16 h3 = __float2bfloat16_rn(v.w);
    __nv_bfloat162* hp = reinterpret_cast<__nv_bfloat162*>(hi) + i * 2;
    __nv_bfloat162* lp = reinterpret_cast<__nv_bfloat162*>(lo) + i * 2;
    hp[0] = __nv_bfloat162(h0, h1);
    hp[1] = __nv_bfloat162(h2, h3);
    lp[0] = __nv_bfloat162(__float2bfloat16_rn(v.x - __bfloat162float(h0)),
                           __float2bfloat16_rn(v.y - __bfloat162float(h1)));
    lp[1] = __nv_bfloat162(__float2bfloat16_rn(v.z - __bfloat162float(h2)),
                           __float2bfloat16_rn(v.w - __bfloat162float(h3)));
}

// ---------------------------------------------------------------------------
// Kernel 1: Q = E @ Wq^T + bq (HMMA, bf16-split 3-MMA), cp.async 2-stage
// pipeline, BK=32, CTA tile 128x128 (R13-proven MMA window), SWIZZLED 64 B
// pitch -> 32 KB/stage -> 3 CTAs/SM -> grid 384 is a SINGLE wave.
// Swizzle: 16B-chunk c of row r lives at r*64 + ((c ^ ((r>>1)&3))*16).
// Stage arrays: A_HI 0, A_LO 8192, B_HI 16384, B_LO 24576 (128 rows each).
// ---------------------------------------------------------------------------
#define QS_STAGE 32768
#define QS_TOTAL 65536

__global__ __launch_bounds__(256, 3) void qproj_hmma_kernel(
    const __nv_bfloat16* __restrict__ Ehi, const __nv_bfloat16* __restrict__ Elo,
    const __nv_bfloat16* __restrict__ Whi, const __nv_bfloat16* __restrict__ Wlo,
    const float* __restrict__ bq, int T)
{
    extern __shared__ __align__(16) char qsm[];
    const uint32_t sb = smem_u32(qsm);
    const int tid = threadIdx.x;
    const int wid = tid >> 5, lane = tid & 31;
    const int wm = wid & 1, wn = wid >> 1;
    const int mbase = blockIdx.y * 128;
    const int nbase = blockIdx.x * 128;

    float acc[4][4][4];
#pragma unroll
    for (int mi = 0; mi < 4; mi++)
#pragma unroll
        for (int ni = 0; ni < 4; ni++)
#pragma unroll
            for (int q = 0; q < 4; q++) acc[mi][ni][q] = 0.f;

    // Per-lane fragment address components (swizzle sel depends only on
    // lane-local row bits; all tile offsets are multiples of 8 rows).
    const int a_r   = lane & 15;
    const uint32_t a_row = (uint32_t)((wm * 64 + a_r) * 64);
    const uint32_t a_sw  = (uint32_t)((a_r >> 1) & 3);
    const uint32_t a_c0  = (uint32_t)(lane >> 4);
    const int b_r   = (lane & 7) + ((lane >> 4) << 3);
    const uint32_t b_row = (uint32_t)((wn * 32 + b_r) * 64);
    const uint32_t b_sw  = (uint32_t)((b_r >> 1) & 3);
    const uint32_t b_c0  = (uint32_t)((lane >> 3) & 1);

    auto stage_chunk = [&](int c) {
        const int k0 = c * 32;
        const uint32_t db = sb + (uint32_t)(c & 1) * QS_STAGE;
        // 2048 cp16 per chunk: a = array (Ehi, Elo, Whi, Wlo), 128 rows x 4 chunks
#pragma unroll
        for (int i = 0; i < 8; i++) {
            int idx = i * 256 + tid;
            int a = idx >> 9;            // 0..3
            int rem = idx & 511;
            int r = rem >> 2, c4 = rem & 3;
            const __nv_bfloat16* src;
            int g;
            if (a == 0)      { src = Ehi; g = mbase + r; if (g >= T) g = T - 1; }
            else if (a == 1) { src = Elo; g = mbase + r; if (g >= T) g = T - 1; }
            else if (a == 2) { src = Whi; g = nbase + r; }
            else             { src = Wlo; g = nbase + r; }
            uint32_t off = (uint32_t)(a * 8192 + r * 64 +
                                      ((c4 ^ ((r >> 1) & 3)) << 4));
            cp16(db + off, src + (size_t)g * D_DIM + k0 + c4 * 8);
        }
    };

    stage_chunk(0);
    CP_COMMIT();

    const int NC = D_DIM / 32;    // 24
    for (int c = 0; c < NC; c++) {
        CP_WAIT0();
        __syncthreads();
        if (c + 1 < NC) { stage_chunk(c + 1); CP_COMMIT(); }

        const uint32_t st = sb + (uint32_t)(c & 1) * QS_STAGE;
#pragma unroll
        for (int ks = 0; ks < 2; ks++) {
            const uint32_t acol = (((a_c0 + 2 * ks) ^ a_sw) << 4);
            const uint32_t bcol = (((b_c0 + 2 * ks) ^ b_sw) << 4);
            const uint32_t ao = st + a_row + acol;            // A_HI at 0
            const uint32_t bo = st + 16384 + b_row + bcol;    // B_HI
            uint32_t ah[4][4], al[4][4], bh[2][4], bl[2][4];
#pragma unroll
            for (int mi = 0; mi < 4; mi++) ldmx4(ah[mi], ao + mi * 1024);
#pragma unroll
            for (int np = 0; np < 2; np++) ldmx4(bh[np], bo + np * 1024);
#pragma unroll
            for (int mi = 0; mi < 4; mi++)
#pragma unroll
                for (int ni = 0; ni < 4; ni++)
                    mma16816(acc[mi][ni], ah[mi], &bh[ni >> 1][(ni & 1) * 2]);
#pragma unroll
            for (int np = 0; np < 2; np++) ldmx4(bl[np], bo + 8192 + np * 1024);
#pragma unroll
            for (int mi = 0; mi < 4; mi++)
#pragma unroll
                for (int ni = 0; ni < 4; ni++)
                    mma16816(acc[mi][ni], ah[mi], &bl[ni >> 1][(ni & 1) * 2]);
#pragma unroll
            for (int mi = 0; mi < 4; mi++) ldmx4(al[mi], ao + 8192 + mi * 1024);
#pragma unroll
            for (int mi = 0; mi < 4; mi++)
#pragma unroll
                for (int ni = 0; ni < 4; ni++)
                    mma16816(acc[mi][ni], al[mi], &bh[ni >> 1][(ni & 1) * 2]);
        }
    }

    const int mrow0 = mbase + wm * 64 + (lane >> 2);
    const int ncol0 = nbase + wn * 32 + 2 * (lane & 3);
#pragma unroll
    for (int ni = 0; ni < 4; ni++) {
        int col = ncol0 + ni * 8;
        float2 bv = *reinterpret_cast<const float2*>(&bq[col]);
#pragma unroll
        for (int mi = 0; mi < 4; mi++) {
#pragma unroll
            for (int h = 0; h < 2; h++) {
                int r = mrow0 + mi * 16 + h * 8;
                if (r < T) {
                    float vx = acc[mi][ni][h * 2 + 0] + bv.x;
                    float vy = acc[mi][ni][h * 2 + 1] + bv.y;
                    __nv_bfloat16 hx = __float2bfloat16_rn(vx);
                    __nv_bfloat16 hy = __float2bfloat16_rn(vy);
                    size_t o = (size_t)r * D_DIM + col;
                    *reinterpret_cast<__nv_bfloat162*>(&g_Qhi[o]) = __nv_bfloat162(hx, hy);
                    *reinterpret_cast<__nv_bfloat162*>(&g_Qlo[o]) = __nv_bfloat162(
                        __float2bfloat16_rn(vx - __bfloat162float(hx)),
                        __float2bfloat16_rn(vy - __bfloat162float(hy)));
                }
            }
        }
    }
}

// ---------------------------------------------------------------------------
// Kernel 1b: score band, K-SPLIT x4 (R14-proven).  blockIdx.y = K quarter
// (192 dims, 6 chunks of 32); partial to g_Band0..3 (span sums them).
// Per CTA: M=32 (Q rows t0..t0+31) x N=128 (E rows t0-32..t0+95).
// ---------------------------------------------------------------------------
#define PIT 80
#define BQ_HI 0
#define BQ_LO 2560
#define BE_HI 5120
#define BE_LO 15360
#define B_STAGE 25600
#define B_TOTAL 51200

__global__ __launch_bounds__(256, 3) void band_kernel(
    const __nv_bfloat16* __restrict__ Qh, const __nv_bfloat16* __restrict__ Ql,
    const __nv_bfloat16* __restrict__ Eh, const __nv_bfloat16* __restrict__ El,
    int T)
{
    extern __shared__ __align__(16) char bsm[];
    const uint32_t sb = smem_u32(bsm);
    const int tid = threadIdx.x;
    const int wid = tid >> 5, lane = tid & 31;
    const int wm = wid & 1, wn = wid >> 1;
    const int t0 = blockIdx.x * 32;
    const int kh = blockIdx.y;            // 0..3
    float* bp = (kh == 0) ? g_Band0 : (kh == 1) ? g_Band1 :
                (kh == 2) ? g_Band2 : g_Band3;

    float acc[4][4];
#pragma unroll
    for (int ni = 0; ni < 4; ni++)
#pragma unroll
        for (int q = 0; q < 4; q++) acc[ni][q] = 0.f;

    const uint32_t a_lane = (uint32_t)((wm * 16 + (lane & 15)) * PIT + (lane >> 4) * 16);
    const uint32_t b_lane = (uint32_t)((wn * 32 + (lane & 7) + ((lane >> 4) << 3)) * PIT +
                                       ((lane >> 3) & 1) * 16);

    auto stage_chunk = [&](int c) {
        const int k0 = (kh * 6 + c) * 32;
        const uint32_t db = sb + (uint32_t)(c & 1) * B_STAGE;
#pragma unroll
        for (int i = 0; i < 5; i++) {
            int idx = i * 256 + tid;
            int row = idx >> 2, c4 = idx & 3;
            uint32_t base;
            const __nv_bfloat16* src;
            int g;
            if (row < 64) {
                int r = row & 31;
                base = (row < 32) ? BQ_HI : BQ_LO;
                src  = (row < 32) ? Qh : Ql;
                g = t0 + r;
                if (g >= T) g = T - 1;
                base += (uint32_t)(r * PIT);
            } else {
                int r = (row - 64) & 127;
                base = (row < 192) ? BE_HI : BE_LO;
                src  = (row < 192) ? Eh : El;
                g = t0 - 32 + r;
                if (g < 0) g = 0;
                if (g >= T) g = T - 1;
                base += (uint32_t)(r * PIT);
            }
            cp16(db + base + c4 * 16, src + (size_t)g * D_DIM + k0 + c4 * 8);
        }
    };

    stage_chunk(0);
    CP_COMMIT();

    const int NC = 6;
    for (int c = 0; c < NC; c++) {
        CP_WAIT0();
        __syncthreads();
        if (c + 1 < NC) { stage_chunk(c + 1); CP_COMMIT(); }

        const uint32_t st = sb + (uint32_t)(c & 1) * B_STAGE;
#pragma unroll
        for (int ks = 0; ks < 2; ks++) {
            const uint32_t ao = st + a_lane + ks * 32;
            const uint32_t bo = st + b_lane + ks * 32;
            uint32_t ah[4], al[4], bh[2][4], bl[2][4];
            ldmx4(ah, ao + BQ_HI);
#pragma unroll
            for (int np = 0; np < 2; np++) ldmx4(bh[np], bo + BE_HI + np * 16 * PIT);
#pragma unroll
            for (int ni = 0; ni < 4; ni++)
                mma16816(acc[ni], ah, &bh[ni >> 1][(ni & 1) * 2]);
#pragma unroll
            for (int np = 0; np < 2; np++) ldmx4(bl[np], bo + BE_LO + np * 16 * PIT);
#pragma unroll
            for (int ni = 0; ni < 4; ni++)
                mma16816(acc[ni], ah, &bl[ni >> 1][(ni & 1) * 2]);
            ldmx4(al, ao + BQ_LO);
#pragma unroll
            for (int ni = 0; ni < 4; ni++)
                mma16816(acc[ni], al, &bh[ni >> 1][(ni & 1) * 2]);
        }
    }

    // Epilogue: value at (r, c) = Q[t0+r] . E[t0-32+c]; band col = c - r.
    const int r_base = wm * 16 + (lane >> 2);
    const int c_base = wn * 32 + 2 * (lane & 3);
#pragma unroll
    for (int ni = 0; ni < 4; ni++) {
        int c = c_base + ni * 8;
#pragma unroll
        for (int h = 0; h < 2; h++) {
            int r = r_base + h * 8;
            int t = t0 + r;
            if (t < T) {
                int cc0 = c - r;
                if (cc0 >= 0 && cc0 < 64)
                    bp[(size_t)t * 64 + cc0] = acc[ni][h * 2 + 0];
                int cc1 = cc0 + 1;
                if (cc1 >= 0 && cc1 < 64)
                    bp[(size_t)t * 64 + cc1] = acc[ni][h * 2 + 1];
            }
        }
    }
}

// ---------------------------------------------------------------------------
// Kernel 2: span attention — sums 4 band partials, softmax, csum, epilogue.
// ---------------------------------------------------------------------------
__global__ __launch_bounds__(256) void span_kernel(
    const float* __restrict__ E, const int* __restrict__ spans,
    float* __restrict__ out)
{
    __shared__ float S[32 * 33];
    __shared__ float csum[32];

    const int n = blockIdx.x;
    const int tid = threadIdx.x;
    const int start = spans[2 * n];
    const int len   = spans[2 * n + 1] - start + 1;   // 1..32

    const int warp = tid >> 5, lane = tid & 31;

#pragma unroll
    for (int r = 0; r < 4; r++) {
        int q = warp + 8 * r;
        if (q < len) {
            size_t o = (size_t)(start + q) * 64 + (lane - q + 32);
            float x = (lane < len)
                ? ((g_Band0[o] + g_Band1[o]) + (g_Band2[o] + g_Band3[o]))
                : -INFINITY;
            float m = x;
#pragma unroll
            for (int off = 16; off; off >>= 1)
                m = fmaxf(m, __shfl_xor_sync(0xffffffffu, m, off));
            float e = (lane < len) ? __expf(x - m) : 0.f;
            float ssum = e;
#pragma unroll
            for (int off = 16; off; off >>= 1)
                ssum += __shfl_xor_sync(0xffffffffu, ssum, off);
            S[q * 33 + lane] = e / ssum;
        }
    }
    __syncthreads();

    if (tid < 32) {
        float c = 0.f;
        if (tid < len)
            for (int q = 0; q < len; q++) c += S[q * 33 + tid];
        csum[tid] = c;
    }
    __syncthreads();

    {
        const float* eb = E + (size_t)start * D_DIM + tid;
        float a0 = 0.f, a1 = 0.f, a2 = 0.f;
        for (int k = 0; k < len; k++) {
            float w = csum[k];
            const float* p = eb + (size_t)k * D_DIM;
            a0 += w * p[0];
            a1 += w * p[256];
            a2 += w * p[512];
        }
        float* op = out + (size_t)n * D_DIM + tid;
        op[0]   = a0;
        op[256] = a1;
        op[512] = a2;
    }
}

// ---------------------------------------------------------------------------
// Launch
// ---------------------------------------------------------------------------
extern "C" void kernel_launch(void* const* d_in, const int* in_sizes, int n_in,
                              void* d_out, int out_size)
{
    const float* E     = (const float*)d_in[0];
    const int*   spans = (const int*)d_in[1];
    const float* Wq    = (const float*)d_in[2];
    const float* bq    = (const float*)d_in[3];
    float*       out   = (float*)d_out;

    const int T = in_sizes[0] / D_DIM;
    const int N = in_sizes[1] / 2;

    __nv_bfloat16 *eh, *el, *wh, *wl, *qh, *ql;
    cudaGetSymbolAddress((void**)&eh, g_Ehi);
    cudaGetSymbolAddress((void**)&el, g_Elo);
    cudaGetSymbolAddress((void**)&wh, g_Whi);
    cudaGetSymbolAddress((void**)&wl, g_Wlo);
    cudaGetSymbolAddress((void**)&qh, g_Qhi);
    cudaGetSymbolAddress((void**)&ql, g_Qlo);

    {
        int n4 = T * D_DIM / 4;
        cvt_kernel<<<(n4 + 255) / 256, 256>>>(E, eh, el, n4);
        int w4 = D_DIM * D_DIM / 4;
        cvt_kernel<<<(w4 + 255) / 256, 256>>>(Wq, wh, wl, w4);
    }

    {
        cudaFuncSetAttribute(qproj_hmma_kernel,
                             cudaFuncAttributeMaxDynamicSharedMemorySize, QS_TOTAL);
        dim3 gg(D_DIM / 128, (T + 127) / 128);
        qproj_hmma_kernel<<<gg, 256, QS_TOTAL>>>(eh, el, wh, wl, bq, T);
    }

    {
        cudaFuncSetAttribute(band_kernel,
                             cudaFuncAttributeMaxDynamicSharedMemorySize, B_TOTAL);
        dim3 gb((T + 31) / 32, 4);
        band_kernel<<<gb, 256, B_TOTAL>>>(qh, ql, eh, el, T);
    }

    span_kernel<<<N, 256>>>(E, spans, out);
}

// round 17
// speedup vs baseline: 1.3350x; 1.3350x over previous
#include <cuda_runtime.h>
#include <cuda_bf16.h>
#include <math.h>
#include <stdint.h>

#define D_DIM 768
#define T_MAX 8192
#define NT 256

// Scratch (__device__ globals per harness rules)
__device__ __nv_bfloat16 g_Qhi[(size_t)T_MAX * D_DIM];
__device__ __nv_bfloat16 g_Qlo[(size_t)T_MAX * D_DIM];
__device__ __nv_bfloat16 g_Ehi[(size_t)T_MAX * D_DIM];
__device__ __nv_bfloat16 g_Elo[(size_t)T_MAX * D_DIM];
__device__ __nv_bfloat16 g_Whi[(size_t)D_DIM * D_DIM];
__device__ __nv_bfloat16 g_Wlo[(size_t)D_DIM * D_DIM];
// Score band K-split x4 partials: Band[t][d+32] = Q[t] . E[t+d], d in [-32,32)
__device__ float g_Band0[(size_t)T_MAX * 64];
__device__ float g_Band1[(size_t)T_MAX * 64];
__device__ float g_Band2[(size_t)T_MAX * 64];
__device__ float g_Band3[(size_t)T_MAX * 64];

// ---------------------------------------------------------------------------
// Helpers (baseline PTX only — plain sm_103 target)
// ---------------------------------------------------------------------------
__device__ __forceinline__ uint32_t smem_u32(const void* p) {
    uint32_t a;
    asm("{ .reg .u64 t; cvta.to.shared.u64 t, %1; cvt.u32.u64 %0, t; }"
        : "=r"(a) : "l"(p));
    return a;
}
__device__ __forceinline__ void ldmx4(uint32_t* r, uint32_t addr) {
    asm volatile("ldmatrix.sync.aligned.m8n8.x4.shared.b16 {%0,%1,%2,%3}, [%4];"
                 : "=r"(r[0]), "=r"(r[1]), "=r"(r[2]), "=r"(r[3]) : "r"(addr));
}
__device__ __forceinline__ void mma16816(float* c, const uint32_t* a,
                                         const uint32_t* b) {
    asm volatile(
        "mma.sync.aligned.m16n8k16.row.col.f32.bf16.bf16.f32 "
        "{%0,%1,%2,%3}, {%4,%5,%6,%7}, {%8,%9}, {%0,%1,%2,%3};"
        : "+f"(c[0]), "+f"(c[1]), "+f"(c[2]), "+f"(c[3])
        : "r"(a[0]), "r"(a[1]), "r"(a[2]), "r"(a[3]), "r"(b[0]), "r"(b[1]));
}
__device__ __forceinline__ void cp16(uint32_t dst, const void* src) {
    asm volatile("cp.async.cg.shared.global [%0], [%1], 16;"
                 :: "r"(dst), "l"(src) : "memory");
}
#define CP_COMMIT() asm volatile("cp.async.commit_group;" ::: "memory")
#define CP_WAIT0()  asm volatile("cp.async.wait_group 0;" ::: "memory")

// ---------------------------------------------------------------------------
// Kernel 0: fp32 -> (bf16 hi, bf16 lo) split
// ---------------------------------------------------------------------------
__global__ __launch_bounds__(256) void cvt_kernel(
    const float* __restrict__ src, __nv_bfloat16* __restrict__ hi,
    __nv_bfloat16* __restrict__ lo, int n4)
{
    int i = blockIdx.x * blockDim.x + threadIdx.x;
    if (i >= n4) return;
    float4 v = reinterpret_cast<const float4*>(src)[i];
    __nv_bfloat16 h0 = __float2bfloat16_rn(v.x);
    __nv_bfloat16 h1 = __float2bfloat16_rn(v.y);
    __nv_bfloat16 h2 = __float2bfloat16_rn(v.z);
    __nv_bfloat16 h3 = __float2bfloat16_rn(v.w);
    __nv_bfloat162* hp = reinterpret_cast<__nv_bfloat162*>(hi) + i * 2;
    __nv_bfloat162* lp = reinterpret_cast<__nv_bfloat162*>(lo) + i * 2;
    hp[0] = __nv_bfloat162(h0, h1);
    hp[1] = __nv_bfloat162(h2, h3);
    lp[0] = __nv_bfloat162(__float2bfloat16_rn(v.x - __bfloat162float(h0)),
                           __float2bfloat16_rn(v.y - __bfloat162float(h1)));
    lp[1] = __nv_bfloat162(__float2bfloat16_rn(v.z - __bfloat162float(h2)),
                           __float2bfloat16_rn(v.w - __bfloat162float(h3)));
}

// ---------------------------------------------------------------------------
// Kernel 1: Q = E @ Wq^T + bq (HMMA, bf16-split 3-MMA), cp.async 2-stage
// pipeline, BK=32 (R13 PROVEN CONFIG — do not modify). Tile 128x128, 8 warps.
// ---------------------------------------------------------------------------
#define PIT 80
#define SA_HI 0
#define SA_LO 10240
#define SB_HI 20480
#define SB_LO 30720
#define QS_STAGE 40960
#define QS_TOTAL 81920

__global__ __launch_bounds__(256, 2) void qproj_hmma_kernel(
    const __nv_bfloat16* __restrict__ Ehi, const __nv_bfloat16* __restrict__ Elo,
    const __nv_bfloat16* __restrict__ Whi, const __nv_bfloat16* __restrict__ Wlo,
    const float* __restrict__ bq, int T)
{
    extern __shared__ __align__(16) char qsm[];
    const uint32_t sb = smem_u32(qsm);
    const int tid = threadIdx.x;
    const int wid = tid >> 5, lane = tid & 31;
    const int wm = wid & 1, wn = wid >> 1;
    const int mbase = blockIdx.y * 128;
    const int nbase = blockIdx.x * 128;

    float acc[4][4][4];
#pragma unroll
    for (int mi = 0; mi < 4; mi++)
#pragma unroll
        for (int ni = 0; ni < 4; ni++)
#pragma unroll
            for (int q = 0; q < 4; q++) acc[mi][ni][q] = 0.f;

    const uint32_t a_lane = (uint32_t)((wm * 64 + (lane & 15)) * PIT + (lane >> 4) * 16);
    const uint32_t b_lane = (uint32_t)((wn * 32 + (lane & 7) + ((lane >> 4) << 3)) * PIT +
                                       ((lane >> 3) & 1) * 16);

    auto stage_chunk = [&](int c) {
        const int k0 = c * 32;
        const uint32_t db = sb + (uint32_t)(c & 1) * QS_STAGE;
#pragma unroll
        for (int i = 0; i < 2; i++) {
            int idx = i * 256 + tid;
            int r = idx >> 2, c4 = idx & 3;
            int ar = mbase + r; if (ar >= T) ar = T - 1;
            size_t ga = (size_t)ar * D_DIM + k0 + c4 * 8;
            size_t gb = (size_t)(nbase + r) * D_DIM + k0 + c4 * 8;
            uint32_t so = (uint32_t)(r * PIT + c4 * 16);
            cp16(db + SA_HI + so, Ehi + ga);
            cp16(db + SA_LO + so, Elo + ga);
            cp16(db + SB_HI + so, Whi + gb);
            cp16(db + SB_LO + so, Wlo + gb);
        }
    };

    stage_chunk(0);
    CP_COMMIT();

    const int NC = D_DIM / 32;    // 24
    for (int c = 0; c < NC; c++) {
        CP_WAIT0();
        __syncthreads();
        if (c + 1 < NC) { stage_chunk(c + 1); CP_COMMIT(); }

        const uint32_t st = sb + (uint32_t)(c & 1) * QS_STAGE;
#pragma unroll
        for (int ks = 0; ks < 2; ks++) {
            const uint32_t ao = st + a_lane + ks * 32;
            const uint32_t bo = st + b_lane + ks * 32;
            uint32_t ah[4][4], al[4][4], bh[2][4], bl[2][4];
#pragma unroll
            for (int mi = 0; mi < 4; mi++) ldmx4(ah[mi], ao + SA_HI + mi * 16 * PIT);
#pragma unroll
            for (int np = 0; np < 2; np++) ldmx4(bh[np], bo + SB_HI + np * 16 * PIT);
#pragma unroll
            for (int mi = 0; mi < 4; mi++)
#pragma unroll
                for (int ni = 0; ni < 4; ni++)
                    mma16816(acc[mi][ni], ah[mi], &bh[ni >> 1][(ni & 1) * 2]);
#pragma unroll
            for (int np = 0; np < 2; np++) ldmx4(bl[np], bo + SB_LO + np * 16 * PIT);
#pragma unroll
            for (int mi = 0; mi < 4; mi++)
#pragma unroll
                for (int ni = 0; ni < 4; ni++)
                    mma16816(acc[mi][ni], ah[mi], &bl[ni >> 1][(ni & 1) * 2]);
#pragma unroll
            for (int mi = 0; mi < 4; mi++) ldmx4(al[mi], ao + SA_LO + mi * 16 * PIT);
#pragma unroll
            for (int mi = 0; mi < 4; mi++)
#pragma unroll
                for (int ni = 0; ni < 4; ni++)
                    mma16816(acc[mi][ni], al[mi], &bh[ni >> 1][(ni & 1) * 2]);
        }
    }

    const int mrow0 = mbase + wm * 64 + (lane >> 2);
    const int ncol0 = nbase + wn * 32 + 2 * (lane & 3);
#pragma unroll
    for (int ni = 0; ni < 4; ni++) {
        int col = ncol0 + ni * 8;
        float2 bv = *reinterpret_cast<const float2*>(&bq[col]);
#pragma unroll
        for (int mi = 0; mi < 4; mi++) {
#pragma unroll
            for (int h = 0; h < 2; h++) {
                int r = mrow0 + mi * 16 + h * 8;
                if (r < T) {
                    float vx = acc[mi][ni][h * 2 + 0] + bv.x;
                    float vy = acc[mi][ni][h * 2 + 1] + bv.y;
                    __nv_bfloat16 hx = __float2bfloat16_rn(vx);
                    __nv_bfloat16 hy = __float2bfloat16_rn(vy);
                    size_t o = (size_t)r * D_DIM + col;
                    *reinterpret_cast<__nv_bfloat162*>(&g_Qhi[o]) = __nv_bfloat162(hx, hy);
                    *reinterpret_cast<__nv_bfloat162*>(&g_Qlo[o]) = __nv_bfloat162(
                        __float2bfloat16_rn(vx - __bfloat162float(hx)),
                        __float2bfloat16_rn(vy - __bfloat162float(hy)));
                }
            }
        }
    }
}

// ---------------------------------------------------------------------------
// Kernel 1b: score band, K-SPLIT x4 (R14-proven).  blockIdx.y = K quarter
// (192 dims, 6 chunks of 32); partial to g_Band0..3 (span sums them).
// Per CTA: M=32 (Q rows t0..t0+31) x N=128 (E rows t0-32..t0+95).
// ---------------------------------------------------------------------------
#define BQ_HI 0
#define BQ_LO 2560
#define BE_HI 5120
#define BE_LO 15360
#define B_STAGE 25600
#define B_TOTAL 51200

__global__ __launch_bounds__(256, 3) void band_kernel(
    const __nv_bfloat16* __restrict__ Qh, const __nv_bfloat16* __restrict__ Ql,
    const __nv_bfloat16* __restrict__ Eh, const __nv_bfloat16* __restrict__ El,
    int T)
{
    extern __shared__ __align__(16) char bsm[];
    const uint32_t sb = smem_u32(bsm);
    const int tid = threadIdx.x;
    const int wid = tid >> 5, lane = tid & 31;
    const int wm = wid & 1, wn = wid >> 1;
    const int t0 = blockIdx.x * 32;
    const int kh = blockIdx.y;            // 0..3
    float* bp = (kh == 0) ? g_Band0 : (kh == 1) ? g_Band1 :
                (kh == 2) ? g_Band2 : g_Band3;

    float acc[4][4];
#pragma unroll
    for (int ni = 0; ni < 4; ni++)
#pragma unroll
        for (int q = 0; q < 4; q++) acc[ni][q] = 0.f;

    const uint32_t a_lane = (uint32_t)((wm * 16 + (lane & 15)) * PIT + (lane >> 4) * 16);
    const uint32_t b_lane = (uint32_t)((wn * 32 + (lane & 7) + ((lane >> 4) << 3)) * PIT +
                                       ((lane >> 3) & 1) * 16);

    auto stage_chunk = [&](int c) {
        const int k0 = (kh * 6 + c) * 32;
        const uint32_t db = sb + (uint32_t)(c & 1) * B_STAGE;
#pragma unroll
        for (int i = 0; i < 5; i++) {
            int idx = i * 256 + tid;
            int row = idx >> 2, c4 = idx & 3;
            uint32_t base;
            const __nv_bfloat16* src;
            int g;
            if (row < 64) {
                int r = row & 31;
                base = (row < 32) ? BQ_HI : BQ_LO;
                src  = (row < 32) ? Qh : Ql;
                g = t0 + r;
                if (g >= T) g = T - 1;
                base += (uint32_t)(r * PIT);
            } else {
                int r = (row - 64) & 127;
                base = (row < 192) ? BE_HI : BE_LO;
                src  = (row < 192) ? Eh : El;
                g = t0 - 32 + r;
                if (g < 0) g = 0;
                if (g >= T) g = T - 1;
                base += (uint32_t)(r * PIT);
            }
            cp16(db + base + c4 * 16, src + (size_t)g * D_DIM + k0 + c4 * 8);
        }
    };

    stage_chunk(0);
    CP_COMMIT();

    const int NC = 6;
    for (int c = 0; c < NC; c++) {
        CP_WAIT0();
        __syncthreads();
        if (c + 1 < NC) { stage_chunk(c + 1); CP_COMMIT(); }

        const uint32_t st = sb + (uint32_t)(c & 1) * B_STAGE;
#pragma unroll
        for (int ks = 0; ks < 2; ks++) {
            const uint32_t ao = st + a_lane + ks * 32;
            const uint32_t bo = st + b_lane + ks * 32;
            uint32_t ah[4], al[4], bh[2][4], bl[2][4];
            ldmx4(ah, ao + BQ_HI);
#pragma unroll
            for (int np = 0; np < 2; np++) ldmx4(bh[np], bo + BE_HI + np * 16 * PIT);
#pragma unroll
            for (int ni = 0; ni < 4; ni++)
                mma16816(acc[ni], ah, &bh[ni >> 1][(ni & 1) * 2]);
#pragma unroll
            for (int np = 0; np < 2; np++) ldmx4(bl[np], bo + BE_LO + np * 16 * PIT);
#pragma unroll
            for (int ni = 0; ni < 4; ni++)
                mma16816(acc[ni], ah, &bl[ni >> 1][(ni & 1) * 2]);
            ldmx4(al, ao + BQ_LO);
#pragma unroll
            for (int ni = 0; ni < 4; ni++)
                mma16816(acc[ni], al, &bh[ni >> 1][(ni & 1) * 2]);
        }
    }

    // Epilogue: value at (r, c) = Q[t0+r] . E[t0-32+c]; band col = c - r.
    const int r_base = wm * 16 + (lane >> 2);
    const int c_base = wn * 32 + 2 * (lane & 3);
#pragma unroll
    for (int ni = 0; ni < 4; ni++) {
        int c = c_base + ni * 8;
#pragma unroll
        for (int h = 0; h < 2; h++) {
            int r = r_base + h * 8;
            int t = t0 + r;
            if (t < T) {
                int cc0 = c - r;
                if (cc0 >= 0 && cc0 < 64)
                    bp[(size_t)t * 64 + cc0] = acc[ni][h * 2 + 0];
                int cc1 = cc0 + 1;
                if (cc1 >= 0 && cc1 < 64)
                    bp[(size_t)t * 64 + cc1] = acc[ni][h * 2 + 1];
            }
        }
    }
}

// ---------------------------------------------------------------------------
// Kernel 2: span attention — sums 4 band partials, softmax, csum, epilogue.
// ---------------------------------------------------------------------------
__global__ __launch_bounds__(256) void span_kernel(
    const float* __restrict__ E, const int* __restrict__ spans,
    float* __restrict__ out)
{
    __shared__ float S[32 * 33];
    __shared__ float csum[32];

    const int n = blockIdx.x;
    const int tid = threadIdx.x;
    const int start = spans[2 * n];
    const int len   = spans[2 * n + 1] - start + 1;   // 1..32

    const int warp = tid >> 5, lane = tid & 31;

#pragma unroll
    for (int r = 0; r < 4; r++) {
        int q = warp + 8 * r;
        if (q < len) {
            size_t o = (size_t)(start + q) * 64 + (lane - q + 32);
            float x = (lane < len)
                ? ((g_Band0[o] + g_Band1[o]) + (g_Band2[o] + g_Band3[o]))
                : -INFINITY;
            float m = x;
#pragma unroll
            for (int off = 16; off; off >>= 1)
                m = fmaxf(m, __shfl_xor_sync(0xffffffffu, m, off));
            float e = (lane < len) ? __expf(x - m) : 0.f;
            float ssum = e;
#pragma unroll
            for (int off = 16; off; off >>= 1)
                ssum += __shfl_xor_sync(0xffffffffu, ssum, off);
            S[q * 33 + lane] = e / ssum;
        }
    }
    __syncthreads();

    if (tid < 32) {
        float c = 0.f;
        if (tid < len)
            for (int q = 0; q < len; q++) c += S[q * 33 + tid];
        csum[tid] = c;
    }
    __syncthreads();

    {
        const float* eb = E + (size_t)start * D_DIM + tid;
        float a0 = 0.f, a1 = 0.f, a2 = 0.f;
        for (int k = 0; k < len; k++) {
            float w = csum[k];
            const float* p = eb + (size_t)k * D_DIM;
            a0 += w * p[0];
            a1 += w * p[256];
            a2 += w * p[512];
        }
        float* op = out + (size_t)n * D_DIM + tid;
        op[0]   = a0;
        op[256] = a1;
        op[512] = a2;
    }
}

// ---------------------------------------------------------------------------
// Launch
// ---------------------------------------------------------------------------
extern "C" void kernel_launch(void* const* d_in, const int* in_sizes, int n_in,
                              void* d_out, int out_size)
{
    const float* E     = (const float*)d_in[0];
    const int*   spans = (const int*)d_in[1];
    const float* Wq    = (const float*)d_in[2];
    const float* bq    = (const float*)d_in[3];
    float*       out   = (float*)d_out;

    const int T = in_sizes[0] / D_DIM;
    const int N = in_sizes[1] / 2;

    __nv_bfloat16 *eh, *el, *wh, *wl, *qh, *ql;
    cudaGetSymbolAddress((void**)&eh, g_Ehi);
    cudaGetSymbolAddress((void**)&el, g_Elo);
    cudaGetSymbolAddress((void**)&wh, g_Whi);
    cudaGetSymbolAddress((void**)&wl, g_Wlo);
    cudaGetSymbolAddress((void**)&qh, g_Qhi);
    cudaGetSymbolAddress((void**)&ql, g_Qlo);

    {
        int n4 = T * D_DIM / 4;
        cvt_kernel<<<(n4 + 255) / 256, 256>>>(E, eh, el, n4);
        int w4 = D_DIM * D_DIM / 4;
        cvt_kernel<<<(w4 + 255) / 256, 256>>>(Wq, wh, wl, w4);
    }

    {
        cudaFuncSetAttribute(qproj_hmma_kernel,
                             cudaFuncAttributeMaxDynamicSharedMemorySize, QS_TOTAL);
        dim3 gg(D_DIM / 128, (T + 127) / 128);
        qproj_hmma_kernel<<<gg, 256, QS_TOTAL>>>(eh, el, wh, wl, bq, T);
    }

    {
        cudaFuncSetAttribute(band_kernel,
                             cudaFuncAttributeMaxDynamicSharedMemorySize, B_TOTAL);
        dim3 gb((T + 31) / 32, 4);
        band_kernel<<<gb, 256, B_TOTAL>>>(qh, ql, eh, el, T);
    }

    span_kernel<<<N, 256>>>(E, spans, out);
}